// round 4
// baseline (speedup 1.0000x reference)
#include <cuda_runtime.h>

// ---------------- scratch ----------------
__device__ __align__(16) float d_Y0[16 * 16 * 258 * 258];   // (B,16,258,258)
__device__ __align__(16) float d_Y1[16 * 32 * 130 * 130];   // (B,32,130,130)
__device__ float d_blk0[1024];   // [r2][c2][m16][n16]
__device__ float d_blk1[512];    // [g2][m16][n16]
__device__ float d_part[192];
__device__ float d_bscale[2];

typedef unsigned long long u64;

// ---------------- f32x2 helpers ----------------
__device__ __forceinline__ u64 pk2(float a, float b) {
    u64 r;
    asm("mov.b64 %0, {%1, %2};" : "=l"(r) : "r"(__float_as_uint(a)), "r"(__float_as_uint(b)));
    return r;
}
__device__ __forceinline__ void dfma(u64& d, u64 a, u64 b) {
    asm("fma.rn.f32x2 %0, %1, %2, %0;" : "+l"(d) : "l"(a), "l"(b));
}
__device__ __forceinline__ float2 up2(u64 v) {
    unsigned lo, hi;
    asm("mov.b64 {%0, %1}, %2;" : "=r"(lo), "=r"(hi) : "l"(v));
    return make_float2(__uint_as_float(lo), __uint_as_float(hi));
}

// ---------------- P1: partial sum of squares for b0,b1 ----------------
__global__ __launch_bounds__(256) void k_ssq(const float* __restrict__ b0,
                                             const float* __restrict__ b1) {
    __shared__ float red[256];
    int bid = blockIdx.x, t = threadIdx.x;
    const float* src; long base;
    if (bid < 128) { src = b0; base = (long)bid * 8192; }
    else           { src = b1; base = (long)(bid - 128) * 8192; }
    float s = 0.f;
#pragma unroll
    for (int k = 0; k < 32; k++) { float v = __ldg(src + base + k * 256 + t); s += v * v; }
    red[t] = s; __syncthreads();
    for (int off = 128; off; off >>= 1) { if (t < off) red[t] += red[t + off]; __syncthreads(); }
    if (t == 0) d_part[bid] = red[0];
}

// ---------------- P2: bscale + Gram matrices ----------------
__global__ __launch_bounds__(256) void k_prep(const float* __restrict__ W00,
                                              const float* __restrict__ W10,
                                              const float* __restrict__ W11,
                                              const float* __restrict__ g) {
    int t = threadIdx.x;
    if (t == 0) {
        float s0 = 0.f, s1 = 0.f;
        for (int i = 0; i < 128; i++) s0 += d_part[i];
        for (int i = 128; i < 192; i++) s1 += d_part[i];
        d_bscale[0] = __ldg(g) / sqrtf(s0);
        d_bscale[1] = __ldg(g + 1) / sqrtf(s1);
    }
    // blk0[r][c][m][n] = sum_{o,ij} W00[o,m,ij]W00[o,n,ij]
    //   + sum_{i1:(i1+1)%2==r, j1:(j1+1)%2==c} sum_o W10[o,m,i1j1]W10[o,n,i1j1]
    for (int e = t; e < 1024; e += 256) {
        int n = e & 15, m = (e >> 4) & 15, c = (e >> 8) & 1, r = (e >> 9) & 1;
        float acc = 0.f;
        for (int o = 0; o < 16; o++)
#pragma unroll
            for (int ij = 0; ij < 9; ij++)
                acc += __ldg(W00 + (o * 16 + m) * 9 + ij) * __ldg(W00 + (o * 16 + n) * 9 + ij);
#pragma unroll
        for (int i1 = 0; i1 < 3; i1++) {
            if (((i1 + 1) & 1) != r) continue;
#pragma unroll
            for (int j1 = 0; j1 < 3; j1++) {
                if (((j1 + 1) & 1) != c) continue;
                int ij = i1 * 3 + j1;
                for (int o = 0; o < 32; o++)
                    acc += __ldg(W10 + (o * 16 + m) * 9 + ij) * __ldg(W10 + (o * 16 + n) * 9 + ij);
            }
        }
        d_blk0[e] = acc;   // e == ((r*2+c)*16+m)*16+n
    }
    // blk1[g][m][n]
    for (int e = t; e < 512; e += 256) {
        int n = e & 15, m = (e >> 4) & 15, gg = e >> 8;
        float acc = 0.f;
        for (int o = 0; o < 32; o++)
#pragma unroll
            for (int ij = 0; ij < 9; ij++)
                acc += __ldg(W11 + (o * 32 + gg * 16 + m) * 9 + ij) *
                       __ldg(W11 + (o * 32 + gg * 16 + n) * 9 + ij);
        d_blk1[e] = acc;   // e == (gg*16+m)*16+n
    }
}

// ---------------- Y0 = conv(x0, W00, s1, p2) -> (B,16,258,258) ----------------
__global__ __launch_bounds__(256) void k_y0(const float* __restrict__ x0,
                                            const float* __restrict__ W00) {
    extern __shared__ u64 sm[];   // [o? no: [(ic*9+t9)*16+oc] -> pk2(w,w), 2304
    int t = threadIdx.x;
    for (int idx = t; idx < 2304; idx += 256) {
        int oc = idx & 15, t9 = (idx >> 4) % 9, ic = (idx >> 4) / 9;
        float w = __ldg(W00 + (oc * 16 + ic) * 9 + t9);
        sm[idx] = pk2(w, w);
    }
    __syncthreads();
    int b = blockIdx.z, lane = t & 31, ty = t >> 5;
    int oy = blockIdx.y * 8 + ty;
    int w0 = (blockIdx.x * 32 + lane) * 2;
    u64 acc[16];
#pragma unroll
    for (int i = 0; i < 16; i++) acc[i] = 0ull;
    bool rok[3]; int roff[3];
#pragma unroll
    for (int dy = 0; dy < 3; dy++) { int iy = oy - 2 + dy; rok[dy] = (iy >= 0 && iy < 256); roff[dy] = iy * 256; }
    bool cok[4]; int coff[4];
#pragma unroll
    for (int cc = 0; cc < 4; cc++) { int ix = w0 - 2 + cc; cok[cc] = (ix >= 0 && ix < 256); coff[cc] = ix; }
    const float* xb = x0 + (long)b * 1048576;
#pragma unroll 1
    for (int ic = 0; ic < 16; ic++) {
        const float* xc = xb + ic * 65536;
        float v[3][4];
#pragma unroll
        for (int dy = 0; dy < 3; dy++)
#pragma unroll
            for (int cc = 0; cc < 4; cc++)
                v[dy][cc] = (rok[dy] && cok[cc]) ? __ldg(xc + roff[dy] + coff[cc]) : 0.f;
        const u64* wbase = sm + ic * 144;
#pragma unroll
        for (int dy = 0; dy < 3; dy++)
#pragma unroll
            for (int dx = 0; dx < 3; dx++) {
                u64 a = pk2(v[dy][dx], v[dy][dx + 1]);
                const u64* wp = wbase + (dy * 3 + dx) * 16;
#pragma unroll
                for (int oc = 0; oc < 16; oc++) dfma(acc[oc], wp[oc], a);
            }
    }
    if (oy < 258 && w0 < 258) {
        float* yb = d_Y0 + (long)b * 1065024 + oy * 258 + w0;
#pragma unroll
        for (int oc = 0; oc < 16; oc++) {
            float2 f = up2(acc[oc]);
            *reinterpret_cast<float2*>(yb + oc * 66564) = f;
        }
    }
}

// ---------------- Y1 = conv(x0, W10, s2, p3) -> (B,32,130,130) ----------------
__global__ __launch_bounds__(256) void k_y1a(const float* __restrict__ x0,
                                             const float* __restrict__ W10) {
    extern __shared__ u64 sm[];   // [(ic*9+t9)*32+oc] 4608
    int t = threadIdx.x;
    for (int idx = t; idx < 4608; idx += 256) {
        int oc = idx & 31, t9 = (idx >> 5) % 9, ic = (idx >> 5) / 9;
        float w = __ldg(W10 + (oc * 16 + ic) * 9 + t9);
        sm[idx] = pk2(w, w);
    }
    __syncthreads();
    int b = blockIdx.z, lane = t & 31, ty = t >> 5;
    int u = blockIdx.y * 8 + ty;
    int p = blockIdx.x * 32 + lane;   // pair index; v0 = 2p
    int v0 = 2 * p;
    u64 acc[32];
#pragma unroll
    for (int i = 0; i < 32; i++) acc[i] = 0ull;
    bool rok[3]; int roff[3];
#pragma unroll
    for (int dy = 0; dy < 3; dy++) { int iy = 2 * u - 3 + dy; rok[dy] = (iy >= 0 && iy < 256); roff[dy] = iy * 256; }
    bool cok[5]; int coff[5];
#pragma unroll
    for (int cc = 0; cc < 5; cc++) { int ix = 2 * v0 - 3 + cc; cok[cc] = (ix >= 0 && ix < 256); coff[cc] = ix; }
    const float* xb = x0 + (long)b * 1048576;
#pragma unroll 1
    for (int ic = 0; ic < 16; ic++) {
        const float* xc = xb + ic * 65536;
        float v[3][5];
#pragma unroll
        for (int dy = 0; dy < 3; dy++)
#pragma unroll
            for (int cc = 0; cc < 5; cc++)
                v[dy][cc] = (rok[dy] && cok[cc]) ? __ldg(xc + roff[dy] + coff[cc]) : 0.f;
        const u64* wbase = sm + ic * 288;
#pragma unroll
        for (int dy = 0; dy < 3; dy++)
#pragma unroll
            for (int dx = 0; dx < 3; dx++) {
                u64 a = pk2(v[dy][dx], v[dy][dx + 2]);
                const u64* wp = wbase + (dy * 3 + dx) * 32;
#pragma unroll
                for (int oc = 0; oc < 32; oc++) dfma(acc[oc], wp[oc], a);
            }
    }
    if (u < 130 && p < 65) {
        float* yb = d_Y1 + (long)b * 540800 + u * 130 + v0;
#pragma unroll
        for (int oc = 0; oc < 32; oc++) {
            float2 f = up2(acc[oc]);
            *reinterpret_cast<float2*>(yb + oc * 16900) = f;
        }
    }
}

// ---------------- Y1 += conv(x1, W11, s1, p2); half of oc per block.z ----------
__global__ __launch_bounds__(256) void k_y1b(const float* __restrict__ x1,
                                             const float* __restrict__ W11) {
    extern __shared__ u64 sm[];   // [(ic*9+t9)*16+ocl] 4608
    int t = threadIdx.x;
    int half = blockIdx.z & 1, b = blockIdx.z >> 1;
    for (int idx = t; idx < 4608; idx += 256) {
        int ocl = idx & 15, t9 = (idx >> 4) % 9, ic = (idx >> 4) / 9;
        float w = __ldg(W11 + ((half * 16 + ocl) * 32 + ic) * 9 + t9);
        sm[idx] = pk2(w, w);
    }
    __syncthreads();
    int lane = t & 31, ty = t >> 5;
    int h = blockIdx.y * 8 + ty;
    int p = blockIdx.x * 32 + lane;
    int w0 = 2 * p;
    u64 acc[16];
#pragma unroll
    for (int i = 0; i < 16; i++) acc[i] = 0ull;
    bool rok[3]; int roff[3];
#pragma unroll
    for (int dy = 0; dy < 3; dy++) { int iy = h - 2 + dy; rok[dy] = (iy >= 0 && iy < 128); roff[dy] = iy * 128; }
    bool cok[4]; int coff[4];
#pragma unroll
    for (int cc = 0; cc < 4; cc++) { int ix = w0 - 2 + cc; cok[cc] = (ix >= 0 && ix < 128); coff[cc] = ix; }
    const float* xb = x1 + (long)b * 524288;
#pragma unroll 1
    for (int ic = 0; ic < 32; ic++) {
        const float* xc = xb + ic * 16384;
        float v[3][4];
#pragma unroll
        for (int dy = 0; dy < 3; dy++)
#pragma unroll
            for (int cc = 0; cc < 4; cc++)
                v[dy][cc] = (rok[dy] && cok[cc]) ? __ldg(xc + roff[dy] + coff[cc]) : 0.f;
        const u64* wbase = sm + ic * 144;
#pragma unroll
        for (int dy = 0; dy < 3; dy++)
#pragma unroll
            for (int dx = 0; dx < 3; dx++) {
                u64 a = pk2(v[dy][dx], v[dy][dx + 1]);
                const u64* wp = wbase + (dy * 3 + dx) * 16;
#pragma unroll
                for (int oc = 0; oc < 16; oc++) dfma(acc[oc], wp[oc], a);
            }
    }
    if (h < 130 && p < 65) {
        float* yb = d_Y1 + (long)b * 540800 + (long)(half * 16) * 16900 + h * 130 + w0;
#pragma unroll
        for (int oc = 0; oc < 16; oc++) {
            float2* pp = reinterpret_cast<float2*>(yb + oc * 16900);
            float2 old = *pp;
            float2 f = up2(acc[oc]);
            old.x += f.x; old.y += f.y;
            *pp = old;
        }
    }
}

// -------- Z0a: out0 = -conv_t(Y0,W00,s1,p2) + diag(blk0,x0) + bs0*b0 -----------
__global__ __launch_bounds__(256) void k_z0a(const float* __restrict__ x0,
                                             const float* __restrict__ W00,
                                             const float* __restrict__ b0,
                                             float* __restrict__ out) {
    extern __shared__ u64 sm[];
    u64* sW = sm;            // [(o*9+t9)*16+i] = (-w,-w)           2304
    u64* sB = sm + 2304;     // [r][n][i] = (blk0[r][0][i][n], blk0[r][1][i][n])  512
    int t = threadIdx.x;
    for (int idx = t; idx < 2304; idx += 256) {
        int i = idx & 15, t9 = (idx >> 4) % 9, o = (idx >> 4) / 9;
        float w = -__ldg(W00 + (o * 16 + i) * 9 + t9);
        sW[idx] = pk2(w, w);
    }
    for (int idx = t; idx < 512; idx += 256) {
        int i = idx & 15, n = (idx >> 4) & 15, r = idx >> 8;
        float a0 = d_blk0[((r * 2 + 0) * 16 + i) * 16 + n];
        float a1 = d_blk0[((r * 2 + 1) * 16 + i) * 16 + n];
        sB[idx] = pk2(a0, a1);
    }
    __syncthreads();
    int b = blockIdx.z, lane = t & 31, ty = t >> 5;
    int h = blockIdx.y * 8 + ty;
    int w0 = (blockIdx.x * 32 + lane) * 2;
    u64 acc[16];
#pragma unroll
    for (int i = 0; i < 16; i++) acc[i] = 0ull;
    // conv_t term: Z[i,h,w] += W00[o,i,dy,dx]*Y0[o,h+2-dy,w+2-dx]; always in-bounds
    const float* yb = d_Y0 + (long)b * 1065024 + h * 258 + w0;
#pragma unroll 1
    for (int o = 0; o < 16; o++) {
        const float* yc = yb + o * 66564;
        float yv[3][4];
#pragma unroll
        for (int rr = 0; rr < 3; rr++) {
            float2 a = *reinterpret_cast<const float2*>(yc + rr * 258);
            float2 c = *reinterpret_cast<const float2*>(yc + rr * 258 + 2);
            yv[rr][0] = a.x; yv[rr][1] = a.y; yv[rr][2] = c.x; yv[rr][3] = c.y;
        }
        const u64* wbase = sW + o * 144;
#pragma unroll
        for (int dy = 0; dy < 3; dy++)
#pragma unroll
            for (int dx = 0; dx < 3; dx++) {
                u64 a = pk2(yv[2 - dy][2 - dx], yv[2 - dy][3 - dx]);
                const u64* wp = wbase + (dy * 3 + dx) * 16;
#pragma unroll
                for (int i = 0; i < 16; i++) dfma(acc[i], wp[i], a);
            }
    }
    // diag term (positive)
    {
        int r = h & 1;
        const u64* sb = sB + r * 256;
        const float* xb = x0 + (long)b * 1048576 + h * 256 + w0;
#pragma unroll 1
        for (int n = 0; n < 16; n++) {
            float2 xv = *reinterpret_cast<const float2*>(xb + n * 65536);
            u64 a = pk2(xv.x, xv.y);
            const u64* bp = sb + n * 16;
#pragma unroll
            for (int i = 0; i < 16; i++) dfma(acc[i], bp[i], a);
        }
    }
    float bs = d_bscale[0];
    float* ob = out + (long)b * 1048576 + h * 256 + w0;
    const float* bb0 = b0 + h * 256 + w0;
#pragma unroll
    for (int i = 0; i < 16; i++) {
        float2 bb = *reinterpret_cast<const float2*>(bb0 + i * 65536);
        float2 f = up2(acc[i]);
        f.x = fmaf(bs, bb.x, f.x);
        f.y = fmaf(bs, bb.y, f.y);
        *reinterpret_cast<float2*>(ob + i * 65536) = f;
    }
}

// -------- Z0b: out0 -= conv_t(Y1, W10, s2, p3, op1) ----------------------------
// For output (h,w): valid taps require (h+3-dy) even, (w+3-dx) even; all in-bounds.
__global__ __launch_bounds__(256) void k_z0b(const float* __restrict__ W10,
                                             float* __restrict__ out) {
    extern __shared__ u64 sm[];
    u64* sT = sm;          // [dy][o][i] = (-W[o,i,dy,1], -W[o,i,dy,0])   1536
    u64* sU = sm + 1536;   // [dy][o][i] = (0, -W[o,i,dy,2])              1536
    int t = threadIdx.x;
    for (int idx = t; idx < 1536; idx += 256) {
        int i = idx & 15, o = (idx >> 4) & 31, dy = idx >> 9;
        const float* wb = W10 + ((o * 16 + i) * 3 + dy) * 3;
        float wa = -__ldg(wb + 0), wbv = -__ldg(wb + 1), wc = -__ldg(wb + 2);
        sT[idx] = pk2(wbv, wa);
        sU[idx] = pk2(0.f, wc);
    }
    __syncthreads();
    int b = blockIdx.z, lane = t & 31, ty = t >> 5;
    int h = blockIdx.y * 8 + ty;
    int w0 = (blockIdx.x * 32 + lane) * 2;   // even pixel; pair (w0, w0+1)
    int qc = w0 / 2 + 1;                     // Y1 col for (pixel0,dx=1) and (pixel1,dx=2); pixel1 dx=0 uses qc+1
    int hp = h & 1;
    int ntap = hp ? 2 : 1;
    int dys[2], qys[2];
    if (!hp) { dys[0] = 1; qys[0] = h / 2 + 1; dys[1] = 0; qys[1] = 0; }
    else { dys[0] = 0; qys[0] = (h + 3) >> 1; dys[1] = 2; qys[1] = (h + 1) >> 1; }
    u64 acc[16];
#pragma unroll
    for (int i = 0; i < 16; i++) acc[i] = 0ull;
    const float* yb = d_Y1 + (long)b * 540800;
#pragma unroll 1
    for (int o = 0; o < 32; o++) {
        const float* yc = yb + o * 16900;
#pragma unroll 2
        for (int tt = 0; tt < ntap; tt++) {
            int dy = dys[tt];
            const float* yr = yc + qys[tt] * 130 + qc;
            float yA = __ldg(yr);        // col qc
            float yB = __ldg(yr + 1);    // col qc+1
            u64 a1 = pk2(yA, yB);
            u64 a2 = pk2(yA, yA);
            const u64* tp = sT + (dy * 32 + o) * 16;
            const u64* up = sU + (dy * 32 + o) * 16;
#pragma unroll
            for (int i = 0; i < 16; i++) { dfma(acc[i], tp[i], a1); dfma(acc[i], up[i], a2); }
        }
    }
    float* ob = out + (long)b * 1048576 + h * 256 + w0;
#pragma unroll
    for (int i = 0; i < 16; i++) {
        float2* pp = reinterpret_cast<float2*>(ob + i * 65536);
        float2 old = *pp;
        float2 f = up2(acc[i]);
        old.x += f.x; old.y += f.y;
        *pp = old;
    }
}

// -------- Z1: out1 = -conv_t(Y1,W11,s1,p2) + diag(blk1,x1) + bs1*b1 ------------
// half of output channels per block.z (gc group == half)
__global__ __launch_bounds__(256) void k_z1(const float* __restrict__ x1,
                                            const float* __restrict__ W11,
                                            const float* __restrict__ b1,
                                            float* __restrict__ out) {
    extern __shared__ u64 sm[];
    u64* sW = sm;           // [(o*9+t9)*16+i] = (-w,-w) for i in this half   4608
    u64* sB = sm + 4608;    // [n][i] = (blk1[half][i][n], same)              256
    int t = threadIdx.x;
    int half = blockIdx.z & 1, b = blockIdx.z >> 1;
    for (int idx = t; idx < 4608; idx += 256) {
        int i = idx & 15, t9 = (idx >> 4) % 9, o = (idx >> 4) / 9;
        float w = -__ldg(W11 + (o * 32 + half * 16 + i) * 9 + t9);
        sW[idx] = pk2(w, w);
    }
    for (int idx = t; idx < 256; idx += 256) {
        int i = idx & 15, n = idx >> 4;
        float v = d_blk1[half * 256 + i * 16 + n];
        sB[idx] = pk2(v, v);
    }
    __syncthreads();
    int lane = t & 31, ty = t >> 5;
    int h = blockIdx.y * 8 + ty;
    int w0 = (blockIdx.x * 32 + lane) * 2;
    u64 acc[16];
#pragma unroll
    for (int i = 0; i < 16; i++) acc[i] = 0ull;
    const float* yb = d_Y1 + (long)b * 540800 + h * 130 + w0;
#pragma unroll 1
    for (int o = 0; o < 32; o++) {
        const float* yc = yb + o * 16900;
        float yv[3][4];
#pragma unroll
        for (int rr = 0; rr < 3; rr++) {
            float2 a = *reinterpret_cast<const float2*>(yc + rr * 130);
            float2 c = *reinterpret_cast<const float2*>(yc + rr * 130 + 2);
            yv[rr][0] = a.x; yv[rr][1] = a.y; yv[rr][2] = c.x; yv[rr][3] = c.y;
        }
        const u64* wbase = sW + o * 144;
#pragma unroll
        for (int dy = 0; dy < 3; dy++)
#pragma unroll
            for (int dx = 0; dx < 3; dx++) {
                u64 a = pk2(yv[2 - dy][2 - dx], yv[2 - dy][3 - dx]);
                const u64* wp = wbase + (dy * 3 + dx) * 16;
#pragma unroll
                for (int i = 0; i < 16; i++) dfma(acc[i], wp[i], a);
            }
    }
    // diag (same group's 16 input channels)
    {
        const float* xb = x1 + (long)b * 524288 + (long)(half * 16) * 16384 + h * 128 + w0;
#pragma unroll 1
        for (int n = 0; n < 16; n++) {
            float2 xv = *reinterpret_cast<const float2*>(xb + n * 16384);
            u64 a = pk2(xv.x, xv.y);
            const u64* bp = sB + n * 16;
#pragma unroll
            for (int i = 0; i < 16; i++) dfma(acc[i], bp[i], a);
        }
    }
    float bs = d_bscale[1];
    float* ob = out + (long)b * 524288 + (long)(half * 16) * 16384 + h * 128 + w0;
    const float* bb0 = b1 + (long)(half * 16) * 16384 + h * 128 + w0;
#pragma unroll
    for (int i = 0; i < 16; i++) {
        float2 bb = *reinterpret_cast<const float2*>(bb0 + i * 16384);
        float2 f = up2(acc[i]);
        f.x = fmaf(bs, bb.x, f.x);
        f.y = fmaf(bs, bb.y, f.y);
        *reinterpret_cast<float2*>(ob + i * 16384) = f;
    }
}

// ---------------- launch ----------------
extern "C" void kernel_launch(void* const* d_in, const int* in_sizes, int n_in,
                              void* d_out, int out_size) {
    const float* x0  = (const float*)d_in[0];
    const float* x1  = (const float*)d_in[1];
    const float* W00 = (const float*)d_in[2];
    const float* W10 = (const float*)d_in[3];
    const float* W11 = (const float*)d_in[4];
    const float* b0  = (const float*)d_in[5];
    const float* b1  = (const float*)d_in[6];
    const float* g   = (const float*)d_in[7];
    float* out0 = (float*)d_out;
    float* out1 = out0 + (long)16 * 16 * 256 * 256;

    k_ssq<<<192, 256>>>(b0, b1);
    k_prep<<<1, 256>>>(W00, W10, W11, g);
    k_y0 <<<dim3(5, 33, 16), 256, 2304 * 8>>>(x0, W00);
    k_y1a<<<dim3(3, 17, 16), 256, 4608 * 8>>>(x0, W10);
    k_y1b<<<dim3(3, 17, 32), 256, 4608 * 8>>>(x1, W11);
    k_z0a<<<dim3(4, 32, 16), 256, 2816 * 8>>>(x0, W00, b0, out0);
    k_z0b<<<dim3(4, 32, 16), 256, 3072 * 8>>>(W10, out0);
    k_z1 <<<dim3(2, 16, 32), 256, 4864 * 8>>>(x1, W11, b1, out1);
}

// round 5
// speedup vs baseline: 1.8798x; 1.8798x over previous
#include <cuda_runtime.h>

// ---------------- scratch ----------------
__device__ __align__(16) float d_Y0[16 * 16 * 258 * 258];   // (B,16,258,258)
__device__ __align__(16) float d_Y1[16 * 32 * 130 * 130];   // (B,32,130,130)
__device__ float d_blk0[1024];   // [r2][c2][m16][n16]
__device__ float d_blk1[512];    // [g2][m16][n16]
__device__ float d_part[192];
__device__ float d_bscale[2];

typedef unsigned long long u64;

// ---------------- f32x2 helpers ----------------
__device__ __forceinline__ u64 pk2(float a, float b) {
    u64 r;
    asm("mov.b64 %0, {%1, %2};" : "=l"(r) : "r"(__float_as_uint(a)), "r"(__float_as_uint(b)));
    return r;
}
__device__ __forceinline__ u64 dup2(float a) { return pk2(a, a); }
__device__ __forceinline__ void dfma(u64& d, u64 a, u64 b) {
    asm("fma.rn.f32x2 %0, %1, %2, %0;" : "+l"(d) : "l"(a), "l"(b));
}
__device__ __forceinline__ float2 up2(u64 v) {
    unsigned lo, hi;
    asm("mov.b64 {%0, %1}, %2;" : "=r"(lo), "=r"(hi) : "l"(v));
    return make_float2(__uint_as_float(lo), __uint_as_float(hi));
}

// ---------------- P1: partial sum of squares for b0,b1 ----------------
__global__ __launch_bounds__(256) void k_ssq(const float* __restrict__ b0,
                                             const float* __restrict__ b1) {
    __shared__ float red[256];
    int bid = blockIdx.x, t = threadIdx.x;
    const float* src; long base;
    if (bid < 128) { src = b0; base = (long)bid * 8192; }
    else           { src = b1; base = (long)(bid - 128) * 8192; }
    float s = 0.f;
#pragma unroll
    for (int k = 0; k < 32; k++) { float v = __ldg(src + base + k * 256 + t); s += v * v; }
    red[t] = s; __syncthreads();
    for (int off = 128; off; off >>= 1) { if (t < off) red[t] += red[t + off]; __syncthreads(); }
    if (t == 0) d_part[bid] = red[0];
}

// ---------------- P2: bscale + Gram matrices ----------------
__global__ __launch_bounds__(256) void k_prep(const float* __restrict__ W00,
                                              const float* __restrict__ W10,
                                              const float* __restrict__ W11,
                                              const float* __restrict__ g) {
    int t = threadIdx.x;
    if (t == 0) {
        float s0 = 0.f, s1 = 0.f;
        for (int i = 0; i < 128; i++) s0 += d_part[i];
        for (int i = 128; i < 192; i++) s1 += d_part[i];
        d_bscale[0] = __ldg(g) / sqrtf(s0);
        d_bscale[1] = __ldg(g + 1) / sqrtf(s1);
    }
    for (int e = t; e < 1024; e += 256) {
        int n = e & 15, m = (e >> 4) & 15, c = (e >> 8) & 1, r = (e >> 9) & 1;
        float acc = 0.f;
        for (int o = 0; o < 16; o++)
#pragma unroll
            for (int ij = 0; ij < 9; ij++)
                acc += __ldg(W00 + (o * 16 + m) * 9 + ij) * __ldg(W00 + (o * 16 + n) * 9 + ij);
#pragma unroll
        for (int i1 = 0; i1 < 3; i1++) {
            if (((i1 + 1) & 1) != r) continue;
#pragma unroll
            for (int j1 = 0; j1 < 3; j1++) {
                if (((j1 + 1) & 1) != c) continue;
                int ij = i1 * 3 + j1;
                for (int o = 0; o < 32; o++)
                    acc += __ldg(W10 + (o * 16 + m) * 9 + ij) * __ldg(W10 + (o * 16 + n) * 9 + ij);
            }
        }
        d_blk0[e] = acc;   // ((r*2+c)*16+m)*16+n
    }
    for (int e = t; e < 512; e += 256) {
        int n = e & 15, m = (e >> 4) & 15, gg = e >> 8;
        float acc = 0.f;
        for (int o = 0; o < 32; o++)
#pragma unroll
            for (int ij = 0; ij < 9; ij++)
                acc += __ldg(W11 + (o * 32 + gg * 16 + m) * 9 + ij) *
                       __ldg(W11 + (o * 32 + gg * 16 + n) * 9 + ij);
        d_blk1[e] = acc;   // (gg*16+m)*16+n
    }
}

// ---------------- Y0 = conv(x0, W00, s1, p2) -> (B,16,258,258) ----------------
// 4 pixels x 8 chan-pairs per thread; linearized (row, col-quad) items.
__global__ __launch_bounds__(256, 2) void k_y0(const float* __restrict__ x0,
                                               const float* __restrict__ W00) {
    extern __shared__ u64 sm[];   // 1152: [(ic*9+tap)*8+ip] = (W[2ip][ic][tap], W[2ip+1][ic][tap])
    int t = threadIdx.x;
    for (int idx = t; idx < 1152; idx += 256) {
        int ip = idx & 7, rest = idx >> 3, tap = rest % 9, ic = rest / 9;
        float wa = __ldg(W00 + ((2 * ip) * 16 + ic) * 9 + tap);
        float wb = __ldg(W00 + ((2 * ip + 1) * 16 + ic) * 9 + tap);
        sm[idx] = pk2(wa, wb);
    }
    __syncthreads();
    int b = blockIdx.z;
    int item = blockIdx.x * 256 + t;
    int r = item / 65, q = item - r * 65;
    int w0 = q * 4;
    bool valid = (r < 258);
    u64 acc[4][8];
#pragma unroll
    for (int p = 0; p < 4; p++)
#pragma unroll
        for (int ip = 0; ip < 8; ip++) acc[p][ip] = 0ull;
    const float* xb = x0 + (long)b * 1048576;
#pragma unroll 1
    for (int ic = 0; ic < 16; ic++) {
        const float* xc = xb + ic * 65536;
        const u64* wbase = sm + ic * 72;
#pragma unroll
        for (int dy = 0; dy < 3; dy++) {
            int iy = r - 2 + dy;
            bool rowok = valid && iy >= 0 && iy < 256;
            float v[6];
#pragma unroll
            for (int j = 0; j < 6; j++) {
                int ix = w0 - 2 + j;
                v[j] = (rowok && ix >= 0 && ix < 256) ? __ldg(xc + iy * 256 + ix) : 0.f;
            }
#pragma unroll
            for (int dx = 0; dx < 3; dx++) {
                const u64* wp = wbase + (dy * 3 + dx) * 8;
                u64 wr[8];
#pragma unroll
                for (int ip = 0; ip < 8; ip++) wr[ip] = wp[ip];
#pragma unroll
                for (int p = 0; p < 4; p++) {
                    u64 a = dup2(v[p + dx]);
#pragma unroll
                    for (int ip = 0; ip < 8; ip++) dfma(acc[p][ip], wr[ip], a);
                }
            }
        }
    }
    if (valid) {
        float* yb = d_Y0 + (long)b * 1065024 + r * 258 + w0;
#pragma unroll
        for (int p = 0; p < 4; p++) {
            if (w0 + p >= 258) break;
#pragma unroll
            for (int ip = 0; ip < 8; ip++) {
                float2 f = up2(acc[p][ip]);
                yb[(2 * ip) * 66564 + p] = f.x;
                yb[(2 * ip + 1) * 66564 + p] = f.y;
            }
        }
    }
}

// ------- Y1 = conv(x0,W10,s2,p3) + conv(x1,W11,s1,p2) -> (B,32,130,130) -------
// half of 32 oc per blockIdx.z parity; 4 pixels x 8 chan-pairs.
__global__ __launch_bounds__(256, 2) void k_y1(const float* __restrict__ x0,
                                               const float* __restrict__ x1,
                                               const float* __restrict__ W10,
                                               const float* __restrict__ W11) {
    extern __shared__ u64 sm[];   // sA 1152 (W10 half) + sB 2304 (W11 half)
    u64* sA = sm; u64* sB2 = sm + 1152;
    int t = threadIdx.x;
    int half = blockIdx.z & 1, b = blockIdx.z >> 1;
    for (int idx = t; idx < 1152; idx += 256) {
        int ip = idx & 7, rest = idx >> 3, tap = rest % 9, ic = rest / 9;
        float wa = __ldg(W10 + ((half * 16 + 2 * ip) * 16 + ic) * 9 + tap);
        float wb = __ldg(W10 + ((half * 16 + 2 * ip + 1) * 16 + ic) * 9 + tap);
        sA[idx] = pk2(wa, wb);
    }
    for (int idx = t; idx < 2304; idx += 256) {
        int ip = idx & 7, rest = idx >> 3, tap = rest % 9, ic = rest / 9;   // ic 0..31
        float wa = __ldg(W11 + ((half * 16 + 2 * ip) * 32 + ic) * 9 + tap);
        float wb = __ldg(W11 + ((half * 16 + 2 * ip + 1) * 32 + ic) * 9 + tap);
        sB2[idx] = pk2(wa, wb);
    }
    __syncthreads();
    int item = blockIdx.x * 256 + t;
    int u = item / 33, q = item - u * 33;
    int v0 = q * 4;
    bool valid = (u < 130);
    u64 acc[4][8];
#pragma unroll
    for (int p = 0; p < 4; p++)
#pragma unroll
        for (int ip = 0; ip < 8; ip++) acc[p][ip] = 0ull;
    // phase A: stride-2 conv of x0 (16 ic). ix = 2(v0+p)-3+dx = (2v0-3)+2p+dx
    const float* xa = x0 + (long)b * 1048576;
#pragma unroll 1
    for (int ic = 0; ic < 16; ic++) {
        const float* xc = xa + ic * 65536;
        const u64* wbase = sA + ic * 72;
#pragma unroll
        for (int dy = 0; dy < 3; dy++) {
            int iy = 2 * u - 3 + dy;
            bool rowok = valid && iy >= 0 && iy < 256;
            float v[9];
#pragma unroll
            for (int j = 0; j < 9; j++) {
                int ix = 2 * v0 - 3 + j;
                v[j] = (rowok && ix >= 0 && ix < 256) ? __ldg(xc + iy * 256 + ix) : 0.f;
            }
#pragma unroll
            for (int dx = 0; dx < 3; dx++) {
                const u64* wp = wbase + (dy * 3 + dx) * 8;
                u64 wr[8];
#pragma unroll
                for (int ip = 0; ip < 8; ip++) wr[ip] = wp[ip];
#pragma unroll
                for (int p = 0; p < 4; p++) {
                    u64 a = dup2(v[2 * p + dx]);
#pragma unroll
                    for (int ip = 0; ip < 8; ip++) dfma(acc[p][ip], wr[ip], a);
                }
            }
        }
    }
    // phase B: stride-1 conv of x1 (32 ic). ix = (v0-2) + p + dx
    const float* xb1 = x1 + (long)b * 524288;
#pragma unroll 1
    for (int ic = 0; ic < 32; ic++) {
        const float* xc = xb1 + ic * 16384;
        const u64* wbase = sB2 + ic * 72;
#pragma unroll
        for (int dy = 0; dy < 3; dy++) {
            int iy = u - 2 + dy;
            bool rowok = valid && iy >= 0 && iy < 128;
            float v[6];
#pragma unroll
            for (int j = 0; j < 6; j++) {
                int ix = v0 - 2 + j;
                v[j] = (rowok && ix >= 0 && ix < 128) ? __ldg(xc + iy * 128 + ix) : 0.f;
            }
#pragma unroll
            for (int dx = 0; dx < 3; dx++) {
                const u64* wp = wbase + (dy * 3 + dx) * 8;
                u64 wr[8];
#pragma unroll
                for (int ip = 0; ip < 8; ip++) wr[ip] = wp[ip];
#pragma unroll
                for (int p = 0; p < 4; p++) {
                    u64 a = dup2(v[p + dx]);
#pragma unroll
                    for (int ip = 0; ip < 8; ip++) dfma(acc[p][ip], wr[ip], a);
                }
            }
        }
    }
    if (valid) {
        float* yb = d_Y1 + (long)b * 540800 + (long)(half * 16) * 16900 + u * 130 + v0;
#pragma unroll
        for (int p = 0; p < 4; p++) {
            if (v0 + p >= 130) break;
#pragma unroll
            for (int ip = 0; ip < 8; ip++) {
                float2 f = up2(acc[p][ip]);
                yb[(2 * ip) * 16900 + p] = f.x;
                yb[(2 * ip + 1) * 16900 + p] = f.y;
            }
        }
    }
}

// ---- Z0: out0 = -convt(Y0,W00,s1,p2) - convt(Y1,W10,s2,p3,op1) + diag + bias --
__global__ __launch_bounds__(256, 2) void k_z0(const float* __restrict__ x0,
                                               const float* __restrict__ W00,
                                               const float* __restrict__ W10,
                                               const float* __restrict__ b0,
                                               float* __restrict__ out) {
    extern __shared__ u64 sm[];   // sW 1152 | sBk 512 | sT 2304
    u64* sW = sm; u64* sBk = sm + 1152; u64* sT = sm + 1664;
    int t = threadIdx.x;
    for (int idx = t; idx < 1152; idx += 256) {
        int ip = idx & 7, rest = idx >> 3, tap = rest % 9, o = rest / 9;
        float wa = -__ldg(W00 + (o * 16 + 2 * ip) * 9 + tap);
        float wb = -__ldg(W00 + (o * 16 + 2 * ip + 1) * 9 + tap);
        sW[idx] = pk2(wa, wb);
    }
    for (int idx = t; idx < 512; idx += 256) {
        int ip = idx & 7, n = (idx >> 3) & 15, rc = idx >> 7;
        float a0 = d_blk0[(rc * 16 + 2 * ip) * 16 + n];
        float a1 = d_blk0[(rc * 16 + 2 * ip + 1) * 16 + n];
        sBk[idx] = pk2(a0, a1);
    }
    for (int idx = t; idx < 2304; idx += 256) {
        int ip = idx & 7, rest = idx >> 3, o = rest & 31, tap = rest >> 5;
        float wa = -__ldg(W10 + (o * 16 + 2 * ip) * 9 + tap);
        float wb = -__ldg(W10 + (o * 16 + 2 * ip + 1) * 9 + tap);
        sT[idx] = pk2(wa, wb);
    }
    __syncthreads();
    int b = blockIdx.z, lane = t & 31, warp = t >> 5;
    int h = blockIdx.y * 8 + warp;
    int w0 = (blockIdx.x * 32 + lane) * 4;
    u64 acc[4][8];
#pragma unroll
    for (int p = 0; p < 4; p++)
#pragma unroll
        for (int ip = 0; ip < 8; ip++) acc[p][ip] = 0ull;

    // term1: -convt(Y0,W00). Z[i,h,w] += W00[o,i,dy,dx]*Y0[o,h+2-dy,w+2-dx]; in-bounds.
    const float* yb = d_Y0 + (long)b * 1065024 + h * 258 + w0;
#pragma unroll 1
    for (int o = 0; o < 16; o++) {
        const float* yc = yb + o * 66564;
        const u64* wbase = sW + o * 72;
#pragma unroll
        for (int rr = 0; rr < 3; rr++) {   // Y0 row h+rr; used by dy = 2-rr
            float2 f0 = *(const float2*)(yc + rr * 258);
            float2 f1 = *(const float2*)(yc + rr * 258 + 2);
            float2 f2 = *(const float2*)(yc + rr * 258 + 4);
            float v[6] = {f0.x, f0.y, f1.x, f1.y, f2.x, f2.y};
            int dy = 2 - rr;
#pragma unroll
            for (int dx = 0; dx < 3; dx++) {
                const u64* wp = wbase + (dy * 3 + dx) * 8;
                u64 wr[8];
#pragma unroll
                for (int ip = 0; ip < 8; ip++) wr[ip] = wp[ip];
#pragma unroll
                for (int p = 0; p < 4; p++) {
                    u64 a = dup2(v[p + 2 - dx]);
#pragma unroll
                    for (int ip = 0; ip < 8; ip++) dfma(acc[p][ip], wr[ip], a);
                }
            }
        }
    }
    // term2: -convt(Y1,W10,s2,p3,op1). Valid taps: (h+3-dy) even, (w+3-dx) even.
    {
        int qc = (w0 >> 1) + 1;
        int hp = h & 1;
        int ntap = hp ? 2 : 1;
        int dyA = hp ? 0 : 1;
        int qrA = hp ? ((h + 3) >> 1) : ((h >> 1) + 1);
        const float* y1b = d_Y1 + (long)b * 540800;
#pragma unroll 1
        for (int o = 0; o < 32; o++) {
            const float* yo = y1b + o * 16900;
            for (int tt = 0; tt < ntap; tt++) {
                int dy = tt ? 2 : dyA;
                int qr = tt ? ((h + 1) >> 1) : qrA;
                const float* yr = yo + qr * 130 + qc;
                float yA = __ldg(yr), yB = __ldg(yr + 1), yC = __ldg(yr + 2);
                u64 aA = dup2(yA), aB = dup2(yB), aC = dup2(yC);
                const u64* w0p = sT + ((dy * 3 + 0) * 32 + o) * 8;
                const u64* w1p = sT + ((dy * 3 + 1) * 32 + o) * 8;
                const u64* w2p = sT + ((dy * 3 + 2) * 32 + o) * 8;
#pragma unroll
                for (int ip = 0; ip < 8; ip++) {
                    u64 r0v = w0p[ip], r1v = w1p[ip], r2v = w2p[ip];
                    dfma(acc[0][ip], r1v, aA);
                    dfma(acc[1][ip], r0v, aB);
                    dfma(acc[1][ip], r2v, aA);
                    dfma(acc[2][ip], r1v, aB);
                    dfma(acc[3][ip], r0v, aC);
                    dfma(acc[3][ip], r2v, aB);
                }
            }
        }
    }
    // term3: +diag. r=h&1, c=(w0+p)&1=p&1 (w0 mult of 4)
    {
        int r = h & 1;
        const u64* sb0 = sBk + (r * 2 + 0) * 128;
        const u64* sb1 = sBk + (r * 2 + 1) * 128;
        const float* xq = x0 + (long)b * 1048576 + h * 256 + w0;
#pragma unroll 1
        for (int n = 0; n < 16; n++) {
            float4 xv = *(const float4*)(xq + n * 65536);
            u64 a0 = dup2(xv.x), a1 = dup2(xv.y), a2 = dup2(xv.z), a3 = dup2(xv.w);
            const u64* b0p = sb0 + n * 8;
            const u64* b1p = sb1 + n * 8;
#pragma unroll
            for (int ip = 0; ip < 8; ip++) {
                u64 e = b0p[ip], od = b1p[ip];
                dfma(acc[0][ip], e, a0);
                dfma(acc[1][ip], od, a1);
                dfma(acc[2][ip], e, a2);
                dfma(acc[3][ip], od, a3);
            }
        }
    }
    // bias + store (vectorized float4 per channel)
    float bs = d_bscale[0];
    const float* bb = b0 + h * 256 + w0;
    float* ob = out + (long)b * 1048576 + h * 256 + w0;
#pragma unroll
    for (int ip = 0; ip < 8; ip++) {
        float2 f0 = up2(acc[0][ip]), f1 = up2(acc[1][ip]), f2 = up2(acc[2][ip]), f3 = up2(acc[3][ip]);
        float4 bv0 = *(const float4*)(bb + (2 * ip) * 65536);
        float4 bv1 = *(const float4*)(bb + (2 * ip + 1) * 65536);
        float4 o0 = make_float4(fmaf(bs, bv0.x, f0.x), fmaf(bs, bv0.y, f1.x),
                                fmaf(bs, bv0.z, f2.x), fmaf(bs, bv0.w, f3.x));
        float4 o1 = make_float4(fmaf(bs, bv1.x, f0.y), fmaf(bs, bv1.y, f1.y),
                                fmaf(bs, bv1.z, f2.y), fmaf(bs, bv1.w, f3.y));
        *(float4*)(ob + (2 * ip) * 65536) = o0;
        *(float4*)(ob + (2 * ip + 1) * 65536) = o1;
    }
}

// -------- Z1: out1 = -convt(Y1,W11,s1,p2) + diag(blk1,x1) + bias ---------------
__global__ __launch_bounds__(256, 2) void k_z1(const float* __restrict__ x1,
                                               const float* __restrict__ W11,
                                               const float* __restrict__ b1,
                                               float* __restrict__ out1) {
    extern __shared__ u64 sm[];   // sW 2304 + sB 128
    u64* sW = sm; u64* sB = sm + 2304;
    int t = threadIdx.x;
    int half = blockIdx.z & 1, b = blockIdx.z >> 1;
    for (int idx = t; idx < 2304; idx += 256) {
        int ip = idx & 7, rest = idx >> 3, tap = rest % 9, o = rest / 9;
        float wa = -__ldg(W11 + (o * 32 + half * 16 + 2 * ip) * 9 + tap);
        float wb = -__ldg(W11 + (o * 32 + half * 16 + 2 * ip + 1) * 9 + tap);
        sW[idx] = pk2(wa, wb);
    }
    for (int idx = t; idx < 128; idx += 256) {
        int ip = idx & 7, n = idx >> 3;
        float a0 = d_blk1[half * 256 + (2 * ip) * 16 + n];
        float a1 = d_blk1[half * 256 + (2 * ip + 1) * 16 + n];
        sB[idx] = pk2(a0, a1);
    }
    __syncthreads();
    int lane = t & 31, warp = t >> 5;
    int h = blockIdx.y * 8 + warp;    // < 128
    int w0 = lane * 4;                // < 128
    u64 acc[4][8];
#pragma unroll
    for (int p = 0; p < 4; p++)
#pragma unroll
        for (int ip = 0; ip < 8; ip++) acc[p][ip] = 0ull;
    const float* yb = d_Y1 + (long)b * 540800 + h * 130 + w0;
#pragma unroll 1
    for (int o = 0; o < 32; o++) {
        const float* yc = yb + o * 16900;
        const u64* wbase = sW + o * 72;
#pragma unroll
        for (int rr = 0; rr < 3; rr++) {
            float2 f0 = *(const float2*)(yc + rr * 130);
            float2 f1 = *(const float2*)(yc + rr * 130 + 2);
            float2 f2 = *(const float2*)(yc + rr * 130 + 4);
            float v[6] = {f0.x, f0.y, f1.x, f1.y, f2.x, f2.y};
            int dy = 2 - rr;
#pragma unroll
            for (int dx = 0; dx < 3; dx++) {
                const u64* wp = wbase + (dy * 3 + dx) * 8;
                u64 wr[8];
#pragma unroll
                for (int ip = 0; ip < 8; ip++) wr[ip] = wp[ip];
#pragma unroll
                for (int p = 0; p < 4; p++) {
                    u64 a = dup2(v[p + 2 - dx]);
#pragma unroll
                    for (int ip = 0; ip < 8; ip++) dfma(acc[p][ip], wr[ip], a);
                }
            }
        }
    }
    // diag
    {
        const float* xq = x1 + (long)b * 524288 + (long)(half * 16) * 16384 + h * 128 + w0;
#pragma unroll 1
        for (int n = 0; n < 16; n++) {
            float4 xv = *(const float4*)(xq + n * 16384);
            u64 a0 = dup2(xv.x), a1 = dup2(xv.y), a2 = dup2(xv.z), a3 = dup2(xv.w);
            const u64* bp = sB + n * 8;
#pragma unroll
            for (int ip = 0; ip < 8; ip++) {
                u64 e = bp[ip];
                dfma(acc[0][ip], e, a0);
                dfma(acc[1][ip], e, a1);
                dfma(acc[2][ip], e, a2);
                dfma(acc[3][ip], e, a3);
            }
        }
    }
    float bs = d_bscale[1];
    const float* bb = b1 + (long)(half * 16) * 16384 + h * 128 + w0;
    float* ob = out1 + (long)b * 524288 + (long)(half * 16) * 16384 + h * 128 + w0;
#pragma unroll
    for (int ip = 0; ip < 8; ip++) {
        float2 f0 = up2(acc[0][ip]), f1 = up2(acc[1][ip]), f2 = up2(acc[2][ip]), f3 = up2(acc[3][ip]);
        float4 bv0 = *(const float4*)(bb + (2 * ip) * 16384);
        float4 bv1 = *(const float4*)(bb + (2 * ip + 1) * 16384);
        float4 o0 = make_float4(fmaf(bs, bv0.x, f0.x), fmaf(bs, bv0.y, f1.x),
                                fmaf(bs, bv0.z, f2.x), fmaf(bs, bv0.w, f3.x));
        float4 o1 = make_float4(fmaf(bs, bv1.x, f0.y), fmaf(bs, bv1.y, f1.y),
                                fmaf(bs, bv1.z, f2.y), fmaf(bs, bv1.w, f3.y));
        *(float4*)(ob + (2 * ip) * 16384) = o0;
        *(float4*)(ob + (2 * ip + 1) * 16384) = o1;
    }
}

// ---------------- launch ----------------
extern "C" void kernel_launch(void* const* d_in, const int* in_sizes, int n_in,
                              void* d_out, int out_size) {
    const float* x0  = (const float*)d_in[0];
    const float* x1  = (const float*)d_in[1];
    const float* W00 = (const float*)d_in[2];
    const float* W10 = (const float*)d_in[3];
    const float* W11 = (const float*)d_in[4];
    const float* b0  = (const float*)d_in[5];
    const float* b1  = (const float*)d_in[6];
    const float* g   = (const float*)d_in[7];
    float* out0 = (float*)d_out;
    float* out1 = out0 + (long)16 * 16 * 256 * 256;

    k_ssq<<<192, 256>>>(b0, b1);
    k_prep<<<1, 256>>>(W00, W10, W11, g);
    k_y0<<<dim3(66, 1, 16), 256, 1152 * 8>>>(x0, W00);          // 258*65 items
    k_y1<<<dim3(17, 1, 32), 256, 3456 * 8>>>(x0, x1, W10, W11); // 130*33 items, halves
    k_z0<<<dim3(2, 32, 16), 256, 3968 * 8>>>(x0, W00, W10, b0, out0);
    k_z1<<<dim3(1, 16, 32), 256, 2432 * 8>>>(x1, W11, b1, out1);
}